// round 1
// baseline (speedup 1.0000x reference)
#include <cuda_runtime.h>
#include <math.h>

#define BB 4
#define NN 2048
#define DD 1024
#define HH 64
#define M_TOT (BB*NN)          // 8192 rows total
#define NEGINF (-INFINITY)

static __device__ float g_q[M_TOT*HH];
static __device__ float g_k[M_TOT*HH];
static __device__ float g_v[M_TOT*HH];
static __device__ float g_S[(size_t)BB*NN*NN];     // 64 MB scores scratch
static __device__ float g_m[M_TOT];
static __device__ float g_rZ[M_TOT];
static __device__ float g_part[4][M_TOT*HH];       // split-K partials for PV

// ---------------------------------------------------------------------------
// Kernel 1: QKV projection. GEMM M=8192, N=64 (per projection), K=1024.
// Tile: 64(M) x 64(N) x 16(K). 256 threads, 4x4 per thread.
// ---------------------------------------------------------------------------
__global__ __launch_bounds__(256) void qkv_kernel(
    const float* __restrict__ x,
    const float* __restrict__ Wq, const float* __restrict__ bq,
    const float* __restrict__ Wk, const float* __restrict__ bk,
    const float* __restrict__ Wv, const float* __restrict__ bv)
{
    const int proj = blockIdx.y;
    const float* W    = (proj == 0) ? Wq : (proj == 1) ? Wk : Wv;
    const float* bias = (proj == 0) ? bq : (proj == 1) ? bk : bv;
    float* out        = (proj == 0) ? g_q : (proj == 1) ? g_k : g_v;

    __shared__ float as[64][17];   // [m][k], padded
    __shared__ float bs[16][64];   // [k][n]

    const int tid = threadIdx.x;
    const int tx = tid & 15;       // n direction (4 cols each)
    const int ty = tid >> 4;       // m direction (4 rows each)
    const int row0 = blockIdx.x * 64;

    float acc[4][4] = {};

    for (int kt = 0; kt < DD; kt += 16) {
        #pragma unroll
        for (int e = 0; e < 4; e++) {
            int idx = tid + e * 256;           // 0..1023
            int r = idx >> 4, c = idx & 15;
            as[r][c] = x[(size_t)(row0 + r) * DD + kt + c];
        }
        #pragma unroll
        for (int e = 0; e < 4; e++) {
            int idx = tid + e * 256;
            int r = idx >> 6, c = idx & 63;
            bs[r][c] = W[(size_t)(kt + r) * HH + c];
        }
        __syncthreads();
        #pragma unroll
        for (int kk = 0; kk < 16; kk++) {
            float a[4];
            #pragma unroll
            for (int i = 0; i < 4; i++) a[i] = as[ty * 4 + i][kk];
            float4 b4 = *(const float4*)&bs[kk][tx * 4];
            float b[4] = {b4.x, b4.y, b4.z, b4.w};
            #pragma unroll
            for (int i = 0; i < 4; i++)
                #pragma unroll
                for (int j = 0; j < 4; j++)
                    acc[i][j] += a[i] * b[j];
        }
        __syncthreads();
    }

    #pragma unroll
    for (int i = 0; i < 4; i++) {
        int r = row0 + ty * 4 + i;
        #pragma unroll
        for (int j = 0; j < 4; j++) {
            int c = tx * 4 + j;
            out[(size_t)r * HH + c] = acc[i][j] + bias[c];
        }
    }
}

// ---------------------------------------------------------------------------
// Kernel 2: scores. S[b][j][i] = mask(q[j]·k[i]).
// mask: (i < j) or (raw == 0)  -> -inf ; else raw * 64^-0.5
// 64x64 tiles, K=64 in one shot. Only upper-triangular tiles (ti >= tj).
// ---------------------------------------------------------------------------
__global__ __launch_bounds__(256) void scores_kernel()
{
    const int ti = blockIdx.x, tj = blockIdx.y, b = blockIdx.z;
    if (ti < tj) return;

    __shared__ float qs[64][65];
    __shared__ float ks[64][65];

    const int tid = threadIdx.x;
    const int tx = tid & 15, ty = tid >> 4;
    const int j0 = tj * 64, i0 = ti * 64;

    const float* qp = g_q + ((size_t)b * NN + j0) * HH;
    const float* kp = g_k + ((size_t)b * NN + i0) * HH;
    #pragma unroll
    for (int e = 0; e < 16; e++) {
        int idx = tid + e * 256;               // 0..4095
        int r = idx >> 6, c = idx & 63;
        qs[r][c] = qp[(size_t)r * HH + c];
        ks[r][c] = kp[(size_t)r * HH + c];
    }
    __syncthreads();

    float acc[4][4] = {};
    #pragma unroll 8
    for (int h = 0; h < 64; h++) {
        float a[4], bv[4];
        #pragma unroll
        for (int i = 0; i < 4; i++) a[i]  = qs[ty * 4 + i][h];
        #pragma unroll
        for (int j = 0; j < 4; j++) bv[j] = ks[tx * 4 + j][h];
        #pragma unroll
        for (int i = 0; i < 4; i++)
            #pragma unroll
            for (int j = 0; j < 4; j++)
                acc[i][j] += a[i] * bv[j];
    }

    float* Sp = g_S + (size_t)b * NN * NN;
    const float scale = 0.125f;                 // 64^-0.5
    #pragma unroll
    for (int i = 0; i < 4; i++) {
        int j = j0 + ty * 4 + i;
        float4 v4;
        float tmp[4];
        #pragma unroll
        for (int jj = 0; jj < 4; jj++) {
            int ii = i0 + tx * 4 + jj;
            float raw = acc[i][jj];
            tmp[jj] = (ii < j || raw == 0.0f) ? NEGINF : raw * scale;
        }
        v4 = make_float4(tmp[0], tmp[1], tmp[2], tmp[3]);
        *(float4*)&Sp[(size_t)j * NN + i0 + tx * 4] = v4;
    }
}

// ---------------------------------------------------------------------------
// Kernel 3: per-row softmax stats over columns i in [j, N): m = max, Z = sumexp
// ---------------------------------------------------------------------------
__device__ __forceinline__ void mz_combine(float& m, float& Z, float m2, float Z2)
{
    if (m2 == NEGINF) return;
    if (m == NEGINF) { m = m2; Z = Z2; return; }
    if (m2 > m) { Z = Z * __expf(m - m2) + Z2; m = m2; }
    else        { Z += Z2 * __expf(m2 - m); }
}

__global__ __launch_bounds__(128) void stats_kernel()
{
    const int row = blockIdx.x;                 // 0..8191
    const int b = row / NN, j = row % NN;
    const float* Sp = g_S + ((size_t)b * NN + j) * NN;

    float m = NEGINF, Z = 0.0f;
    for (int i = j + threadIdx.x; i < NN; i += 128) {
        float s = Sp[i];
        if (s != NEGINF) {
            if (s > m) { Z = Z * __expf(m - s) + 1.0f; m = s; }
            else       { Z += __expf(s - m); }
        }
    }

    __shared__ float sm[128], sz[128];
    const int tid = threadIdx.x;
    sm[tid] = m; sz[tid] = Z;
    __syncthreads();
    for (int s = 64; s > 0; s >>= 1) {
        if (tid < s) mz_combine(sm[tid], sz[tid], sm[tid + s], sz[tid + s]);
        __syncthreads();
    }
    if (tid == 0) {
        g_m[row]  = sm[0];
        g_rZ[row] = 1.0f / sz[0];
    }
}

// ---------------------------------------------------------------------------
// Kernel 4: out[b,i,h] = sum_{j<=i} exp(S[j,i]-m_j)*rZ_j * v[j,h]
// Tile 64(i) x 64(h); K loop over j tiles, split-K 4 ways for balance.
// ---------------------------------------------------------------------------
__global__ __launch_bounds__(256) void pv_kernel()
{
    const int it    = blockIdx.x;               // 0..31
    const int split = blockIdx.y;               // 0..3
    const int b     = blockIdx.z;
    const int n_jt  = it + 1;
    const int chunk = (n_jt + 3) >> 2;
    const int jt0   = split * chunk;
    const int jt1   = min(n_jt, jt0 + chunk);

    __shared__ float ps[64][64];
    __shared__ float vs[64][64];
    __shared__ float msh[64], rzsh[64];

    const int tid = threadIdx.x;
    const int tx = tid & 15, ty = tid >> 4;     // tx -> h, ty -> i
    const int i0 = it * 64;
    const float* Sp = g_S + (size_t)b * NN * NN;

    float acc[4][4] = {};

    for (int jt = jt0; jt < jt1; jt++) {
        const int j0 = jt * 64;
        if (tid < 64) {
            msh[tid]  = g_m[b * NN + j0 + tid];
            rzsh[tid] = g_rZ[b * NN + j0 + tid];
        }
        __syncthreads();
        #pragma unroll
        for (int e = 0; e < 16; e++) {
            int idx = tid + e * 256;
            int r = idx >> 6, c = idx & 63;
            float s = Sp[(size_t)(j0 + r) * NN + i0 + c];
            ps[r][c] = __expf(s - msh[r]) * rzsh[r];   // exp(-inf)=0 handles mask
            vs[r][c] = g_v[((size_t)b * NN + j0 + r) * HH + c];
        }
        __syncthreads();
        #pragma unroll 4
        for (int jj = 0; jj < 64; jj++) {
            float4 a4 = *(const float4*)&ps[jj][ty * 4];
            float4 b4 = *(const float4*)&vs[jj][tx * 4];
            float a[4] = {a4.x, a4.y, a4.z, a4.w};
            float bv[4] = {b4.x, b4.y, b4.z, b4.w};
            #pragma unroll
            for (int i = 0; i < 4; i++)
                #pragma unroll
                for (int h = 0; h < 4; h++)
                    acc[i][h] += a[i] * bv[h];
        }
        __syncthreads();
    }

    float* P = g_part[split];
    const size_t base = ((size_t)b * NN + i0) * HH;
    #pragma unroll
    for (int i = 0; i < 4; i++) {
        int r = ty * 4 + i;
        float4 v4 = make_float4(acc[i][0], acc[i][1], acc[i][2], acc[i][3]);
        *(float4*)&P[base + (size_t)r * HH + tx * 4] = v4;
    }
}

// ---------------------------------------------------------------------------
// Kernel 5: reduce split-K partials into the output
// ---------------------------------------------------------------------------
__global__ __launch_bounds__(256) void reduce_kernel(float* __restrict__ out)
{
    size_t idx = (size_t)blockIdx.x * 256 + threadIdx.x;
    out[idx] = g_part[0][idx] + g_part[1][idx] + g_part[2][idx] + g_part[3][idx];
}

// ---------------------------------------------------------------------------
extern "C" void kernel_launch(void* const* d_in, const int* in_sizes, int n_in,
                              void* d_out, int out_size)
{
    const float* x  = (const float*)d_in[0];
    const float* Wq = (const float*)d_in[1];
    const float* bq = (const float*)d_in[2];
    const float* Wk = (const float*)d_in[3];
    const float* bk = (const float*)d_in[4];
    const float* Wv = (const float*)d_in[5];
    const float* bv = (const float*)d_in[6];
    float* out = (float*)d_out;

    qkv_kernel<<<dim3(M_TOT / 64, 3), 256>>>(x, Wq, bq, Wk, bk, Wv, bv);
    scores_kernel<<<dim3(NN / 64, NN / 64, BB), 256>>>();
    stats_kernel<<<M_TOT, 128>>>();
    pv_kernel<<<dim3(NN / 64, 4, BB), 256>>>();
    reduce_kernel<<<(M_TOT * HH) / 256, 256>>>(out);
}

// round 4
// speedup vs baseline: 1.7814x; 1.7814x over previous
#include <cuda_runtime.h>
#include <math.h>

#define BB 4
#define NN 2048
#define DD 1024
#define HH 64
#define M_TOT (BB*NN)
#define NEGINF (-INFINITY)
#define SPLITS 8

static __device__ float g_q[M_TOT*HH];
static __device__ float g_k[M_TOT*HH];
static __device__ float g_v[M_TOT*HH];
static __device__ float g_S[(size_t)BB*NN*NN];     // scores -> probabilities (in-place)
static __device__ float g_part[SPLITS][M_TOT*HH];  // split-K partials for PV

// ---------------------------------------------------------------------------
// Kernel 1: fused QKV projection. M=8192, N=3x64, K=1024.
// Tile 64(M) x 192(N) x 32(K). 256 threads, 4(m) x 12(n) per thread.
// x tile loaded once for all three projections.
// ---------------------------------------------------------------------------
__global__ __launch_bounds__(256) void qkv_kernel(
    const float* __restrict__ x,
    const float* __restrict__ Wq, const float* __restrict__ bq,
    const float* __restrict__ Wk, const float* __restrict__ bk,
    const float* __restrict__ Wv, const float* __restrict__ bv)
{
    __shared__ float ast[32][68];    // [k][m], transposed x tile
    __shared__ float bs[32][192];    // [k][n] (q|k|v)

    const int tid = threadIdx.x;
    const int tx = tid & 15;         // n: cols tx*4 + p*64
    const int ty = tid >> 4;         // m: rows ty*4
    const int row0 = blockIdx.x * 64;

    // bias regs
    float4 bq4 = ((const float4*)bq)[tx];
    float4 bk4 = ((const float4*)bk)[tx];
    float4 bv4 = ((const float4*)bv)[tx];

    float acc[4][12] = {};

    for (int kt = 0; kt < DD; kt += 32) {
        // x tile: 64 m x 32 k, transposed into ast
        #pragma unroll
        for (int e = 0; e < 2; e++) {
            int id = tid + e * 256;          // 0..511
            int r = id >> 3, c4 = id & 7;    // r: m-row, c4: k-float4
            float4 v = *(const float4*)&x[(size_t)(row0 + r) * DD + kt + c4 * 4];
            ast[c4*4+0][r] = v.x; ast[c4*4+1][r] = v.y;
            ast[c4*4+2][r] = v.z; ast[c4*4+3][r] = v.w;
        }
        // W tiles: 32 k x 64 n per projection
        #pragma unroll
        for (int p = 0; p < 3; p++) {
            const float* W = (p == 0) ? Wq : (p == 1) ? Wk : Wv;
            #pragma unroll
            for (int e = 0; e < 2; e++) {
                int id = tid + e * 256;
                int r = id >> 4, c4 = id & 15;
                float4 v = *(const float4*)&W[(size_t)(kt + r) * HH + c4 * 4];
                *(float4*)&bs[r][p * 64 + c4 * 4] = v;
            }
        }
        __syncthreads();
        #pragma unroll 8
        for (int kk = 0; kk < 32; kk++) {
            float4 a4 = *(const float4*)&ast[kk][ty * 4];
            float a[4] = {a4.x, a4.y, a4.z, a4.w};
            float b[12];
            #pragma unroll
            for (int p = 0; p < 3; p++) {
                float4 b4 = *(const float4*)&bs[kk][p * 64 + tx * 4];
                b[p*4+0] = b4.x; b[p*4+1] = b4.y; b[p*4+2] = b4.z; b[p*4+3] = b4.w;
            }
            #pragma unroll
            for (int i = 0; i < 4; i++)
                #pragma unroll
                for (int j = 0; j < 12; j++)
                    acc[i][j] += a[i] * b[j];
        }
        __syncthreads();
    }

    #pragma unroll
    for (int i = 0; i < 4; i++) {
        size_t r = row0 + ty * 4 + i;
        float4 q4 = make_float4(acc[i][0]+bq4.x, acc[i][1]+bq4.y, acc[i][2]+bq4.z, acc[i][3]+bq4.w);
        float4 k4 = make_float4(acc[i][4]+bk4.x, acc[i][5]+bk4.y, acc[i][6]+bk4.z, acc[i][7]+bk4.w);
        float4 v4 = make_float4(acc[i][8]+bv4.x, acc[i][9]+bv4.y, acc[i][10]+bv4.z, acc[i][11]+bv4.w);
        *(float4*)&g_q[r * HH + tx * 4] = q4;
        *(float4*)&g_k[r * HH + tx * 4] = k4;
        *(float4*)&g_v[r * HH + tx * 4] = v4;
    }
}

// ---------------------------------------------------------------------------
// Kernel 2: scores. Tile 128(j) x 128(i), K=64. 256 threads, 8x8 per thread.
// i < j         -> write 0.0f   (final probability for masked region)
// i >= j, raw=0 -> write -inf   (score space; stats converts to prob)
// else          -> write raw * 64^-0.5
// ---------------------------------------------------------------------------
__global__ __launch_bounds__(256) void scores_kernel()
{
    const int ti = blockIdx.x, tj = blockIdx.y, b = blockIdx.z;
    if (ti < tj) return;

    extern __shared__ float sm_[];
    float (*qs)[66] = (float(*)[66])sm_;              // [j][h]
    float (*ks)[66] = (float(*)[66])(sm_ + 128 * 66); // [i][h]

    const int tid = threadIdx.x;
    const int tx = tid & 15, ty = tid >> 4;
    const int j0 = tj * 128, i0 = ti * 128;

    const float* qp = g_q + ((size_t)b * NN + j0) * HH;
    const float* kp = g_k + ((size_t)b * NN + i0) * HH;
    #pragma unroll
    for (int e = 0; e < 8; e++) {
        int id = tid + e * 256;          // 0..2047 float4s
        int r = id >> 4, c4 = id & 15;
        float4 q4 = *(const float4*)&qp[(size_t)r * HH + c4 * 4];
        float4 k4 = *(const float4*)&kp[(size_t)r * HH + c4 * 4];
        qs[r][c4*4+0]=q4.x; qs[r][c4*4+1]=q4.y; qs[r][c4*4+2]=q4.z; qs[r][c4*4+3]=q4.w;
        ks[r][c4*4+0]=k4.x; ks[r][c4*4+1]=k4.y; ks[r][c4*4+2]=k4.z; ks[r][c4*4+3]=k4.w;
    }
    __syncthreads();

    float acc[8][8] = {};                // [j][i]
    #pragma unroll 4
    for (int h = 0; h < 64; h++) {
        float a[8], bb[8];
        #pragma unroll
        for (int u = 0; u < 8; u++) a[u]  = qs[ty * 8 + u][h];
        #pragma unroll
        for (int u = 0; u < 8; u++) bb[u] = ks[tx + 16 * u][h];
        #pragma unroll
        for (int uj = 0; uj < 8; uj++)
            #pragma unroll
            for (int ui = 0; ui < 8; ui++)
                acc[uj][ui] += a[uj] * bb[ui];
    }

    float* Sp = g_S + (size_t)b * NN * NN;
    const float scale = 0.125f;
    #pragma unroll
    for (int uj = 0; uj < 8; uj++) {
        int j = j0 + ty * 8 + uj;
        #pragma unroll
        for (int ui = 0; ui < 8; ui++) {
            int i = i0 + tx + 16 * ui;
            float raw = acc[uj][ui];
            float val = (i < j) ? 0.0f : ((raw == 0.0f) ? NEGINF : raw * scale);
            Sp[(size_t)j * NN + i] = val;
        }
    }
}

// ---------------------------------------------------------------------------
// Kernel 3: per-row stats over i in [j,N), then normalize S in place:
// S[j][i] <- exp(S-m)*rZ  (probabilities). Masked entries become 0.
// ---------------------------------------------------------------------------
__device__ __forceinline__ void mz_combine(float& m, float& Z, float m2, float Z2)
{
    if (m2 == NEGINF) return;
    if (m == NEGINF) { m = m2; Z = Z2; return; }
    if (m2 > m) { Z = Z * __expf(m - m2) + Z2; m = m2; }
    else        { Z += Z2 * __expf(m2 - m); }
}

__global__ __launch_bounds__(128) void stats_kernel()
{
    const int row = blockIdx.x;
    const int b = row / NN, j = row % NN;
    float* Sp = g_S + ((size_t)b * NN + j) * NN;

    float m = NEGINF, Z = 0.0f;
    for (int i = j + threadIdx.x; i < NN; i += 128) {
        float s = Sp[i];
        if (s != NEGINF) {
            if (s > m) { Z = Z * __expf(m - s) + 1.0f; m = s; }
            else       { Z += __expf(s - m); }
        }
    }

    __shared__ float sm[128], sz[128];
    __shared__ float fm, fz;
    const int tid = threadIdx.x;
    sm[tid] = m; sz[tid] = Z;
    __syncthreads();
    for (int s = 64; s > 0; s >>= 1) {
        if (tid < s) mz_combine(sm[tid], sz[tid], sm[tid + s], sz[tid + s]);
        __syncthreads();
    }
    if (tid == 0) {
        fm = sm[0];
        fz = (sm[0] == NEGINF) ? 0.0f : 1.0f / sz[0];
    }
    __syncthreads();

    const float mm = fm, rz = fz;
    for (int i = j + threadIdx.x; i < NN; i += 128) {
        float s = Sp[i];
        Sp[i] = (s == NEGINF) ? 0.0f : __expf(s - mm) * rz;
    }
}

// ---------------------------------------------------------------------------
// Kernel 4: pure GEMM. out[b,i,h] = sum_j P[j,i] * v[j,h].
// Tile 128(i) x 64(h), K-stage 64(j). 256 threads, 8(i) x 4(h) per thread.
// Split-K 8 ways over j-tiles for load balance.
// ---------------------------------------------------------------------------
__global__ __launch_bounds__(256) void pv_kernel()
{
    const int IT    = blockIdx.x;            // 0..15  (i-tile of 128)
    const int split = blockIdx.y;            // 0..7
    const int b     = blockIdx.z;
    const int n_jt  = 2 * IT + 2;            // 64-wide j tiles needed
    const int chunk = (n_jt + SPLITS - 1) / SPLITS;
    const int jt0   = split * chunk;
    const int jt1   = min(n_jt, jt0 + chunk);

    extern __shared__ float sm_[];
    float (*ps)[132] = (float(*)[132])sm_;               // [j][i] probabilities
    float (*vs)[68]  = (float(*)[68])(sm_ + 64 * 132);   // [j][h]

    const int tid = threadIdx.x;
    const int tx = tid & 15;                 // h: tx*4
    const int ty = tid >> 4;                 // i: ty*8
    const int i0 = IT * 128;
    const float* Sp = g_S + (size_t)b * NN * NN;

    float acc[8][4] = {};

    for (int jt = jt0; jt < jt1; jt++) {
        const int j0 = jt * 64;
        #pragma unroll
        for (int e = 0; e < 8; e++) {
            int id = tid + e * 256;          // 2048 float4s (64 x 32)
            int r = id >> 5, c4 = id & 31;
            float4 v = *(const float4*)&Sp[(size_t)(j0 + r) * NN + i0 + c4 * 4];
            *(float4*)&ps[r][c4 * 4] = v;
        }
        #pragma unroll
        for (int e = 0; e < 4; e++) {
            int id = tid + e * 256;          // 1024 float4s (64 x 16)
            int r = id >> 4, c4 = id & 15;
            float4 v = *(const float4*)&g_v[((size_t)b * NN + j0 + r) * HH + c4 * 4];
            *(float4*)&vs[r][c4 * 4] = v;
        }
        __syncthreads();
        #pragma unroll 4
        for (int j = 0; j < 64; j++) {
            float4 a0 = *(const float4*)&ps[j][ty * 8];
            float4 a1 = *(const float4*)&ps[j][ty * 8 + 4];
            float4 b4 = *(const float4*)&vs[j][tx * 4];
            float a[8] = {a0.x, a0.y, a0.z, a0.w, a1.x, a1.y, a1.z, a1.w};
            float bb[4] = {b4.x, b4.y, b4.z, b4.w};
            #pragma unroll
            for (int i = 0; i < 8; i++)
                #pragma unroll
                for (int h = 0; h < 4; h++)
                    acc[i][h] += a[i] * bb[h];
        }
        __syncthreads();
    }

    float* P = g_part[split];
    const size_t base = ((size_t)b * NN + i0) * HH;
    #pragma unroll
    for (int i = 0; i < 8; i++) {
        int r = ty * 8 + i;
        float4 v4 = make_float4(acc[i][0], acc[i][1], acc[i][2], acc[i][3]);
        *(float4*)&P[base + (size_t)r * HH + tx * 4] = v4;
    }
}

// ---------------------------------------------------------------------------
// Kernel 5: reduce split-K partials
// ---------------------------------------------------------------------------
__global__ __launch_bounds__(256) void reduce_kernel(float* __restrict__ out)
{
    size_t idx = (size_t)blockIdx.x * 256 + threadIdx.x;
    float s = 0.0f;
    #pragma unroll
    for (int p = 0; p < SPLITS; p++) s += g_part[p][idx];
    out[idx] = s;
}

// ---------------------------------------------------------------------------
extern "C" void kernel_launch(void* const* d_in, const int* in_sizes, int n_in,
                              void* d_out, int out_size)
{
    const float* x  = (const float*)d_in[0];
    const float* Wq = (const float*)d_in[1];
    const float* bq = (const float*)d_in[2];
    const float* Wk = (const float*)d_in[3];
    const float* bk = (const float*)d_in[4];
    const float* Wv = (const float*)d_in[5];
    const float* bv = (const float*)d_in[6];
    float* out = (float*)d_out;

    const int scores_smem = 2 * 128 * 66 * sizeof(float);          // 67.6 KB
    const int pv_smem     = (64 * 132 + 64 * 68) * sizeof(float);  // 51.2 KB

    // One-time opt-in for >48KB dynamic smem. Runs on the first (correctness)
    // call, never inside graph capture.
    static bool attrs_set = false;
    if (!attrs_set) {
        cudaFuncSetAttribute(scores_kernel, cudaFuncAttributeMaxDynamicSharedMemorySize, scores_smem);
        cudaFuncSetAttribute(pv_kernel,     cudaFuncAttributeMaxDynamicSharedMemorySize, pv_smem);
        attrs_set = true;
    }

    qkv_kernel<<<dim3(M_TOT / 64), 256>>>(x, Wq, bq, Wk, bk, Wv, bv);
    scores_kernel<<<dim3(NN / 128, NN / 128, BB), 256, scores_smem>>>();
    stats_kernel<<<M_TOT, 128>>>();
    pv_kernel<<<dim3(NN / 128, SPLITS, BB), 256, pv_smem>>>();
    reduce_kernel<<<(M_TOT * HH) / 256, 256>>>(out);
}

// round 6
// speedup vs baseline: 3.1661x; 1.7773x over previous
#include <cuda_runtime.h>
#include <math.h>

#define BB 4
#define NN 2048
#define DD 1024
#define HH 64
#define M_TOT (BB*NN)
#define SPLITS 4

static __device__ float g_q[M_TOT*HH];
static __device__ float g_k[M_TOT*HH];
static __device__ float g_v[M_TOT*HH];
static __device__ float g_S[(size_t)BB*NN*NN];     // unnormalized probabilities exp(score)
static __device__ float g_rZ[M_TOT];               // 1/rowsum
static __device__ float g_part[SPLITS][M_TOT*HH];  // split-K partials for PV

// ---------------------------------------------------------------------------
// TF32 helpers
// ---------------------------------------------------------------------------
__device__ __forceinline__ unsigned f2tf(float f) {
    unsigned u; asm("cvt.rna.tf32.f32 %0, %1;" : "=r"(u) : "f"(f)); return u;
}
__device__ __forceinline__ void mma8(float c[4],
                                     unsigned a0, unsigned a1, unsigned a2, unsigned a3,
                                     unsigned b0, unsigned b1) {
    asm volatile(
        "mma.sync.aligned.m16n8k8.row.col.f32.tf32.tf32.f32 "
        "{%0,%1,%2,%3}, {%4,%5,%6,%7}, {%8,%9}, {%0,%1,%2,%3};"
        : "+f"(c[0]), "+f"(c[1]), "+f"(c[2]), "+f"(c[3])
        : "r"(a0), "r"(a1), "r"(a2), "r"(a3), "r"(b0), "r"(b1));
}

// ---------------------------------------------------------------------------
// Kernel 1: fused QKV projection, tf32 MMA. M=8192, N=192 (q|k|v), K=1024.
// Block tile 64(M) x 192(N), K-stage 32. 8 warps: 2(m) x 4(n),
// warp tile 32x48 = 2 mtiles x 6 ntiles. Static smem (34.8 KB).
// ---------------------------------------------------------------------------
__global__ __launch_bounds__(256) void qkv_kernel(
    const float* __restrict__ x,
    const float* __restrict__ Wq, const float* __restrict__ bq,
    const float* __restrict__ Wk, const float* __restrict__ bk,
    const float* __restrict__ Wv, const float* __restrict__ bv)
{
    __shared__ unsigned as_[64][36];    // [m][k], A-style reads -> pad 4
    __shared__ unsigned bs_[32][200];   // [k][n], B-style reads -> pad 8

    const int tid = threadIdx.x;
    const int wid = tid >> 5, lane = tid & 31;
    const int group = lane >> 2, tig = lane & 3;
    const int warp_m = wid >> 2;        // 0..1  (32 rows each)
    const int warp_n = wid & 3;         // 0..3  (48 cols each)
    const int row0 = blockIdx.x * 64;

    float acc[2][6][4] = {};

    for (int kt = 0; kt < DD; kt += 32) {
        #pragma unroll
        for (int e = 0; e < 2; e++) {
            int id = tid + e * 256;                // 512 float4s (64m x 8 k-f4)
            int r = id >> 3, c4 = id & 7;
            float4 v = *(const float4*)&x[(size_t)(row0 + r) * DD + kt + c4 * 4];
            as_[r][c4*4+0] = f2tf(v.x); as_[r][c4*4+1] = f2tf(v.y);
            as_[r][c4*4+2] = f2tf(v.z); as_[r][c4*4+3] = f2tf(v.w);
        }
        #pragma unroll
        for (int p = 0; p < 3; p++) {
            const float* W = (p == 0) ? Wq : (p == 1) ? Wk : Wv;
            #pragma unroll
            for (int e = 0; e < 2; e++) {
                int id = tid + e * 256;            // 512 float4s (32k x 16 n-f4)
                int r = id >> 4, c4 = id & 15;
                float4 v = *(const float4*)&W[(size_t)(kt + r) * HH + c4 * 4];
                bs_[r][p*64 + c4*4+0] = f2tf(v.x); bs_[r][p*64 + c4*4+1] = f2tf(v.y);
                bs_[r][p*64 + c4*4+2] = f2tf(v.z); bs_[r][p*64 + c4*4+3] = f2tf(v.w);
            }
        }
        __syncthreads();

        #pragma unroll
        for (int kk = 0; kk < 4; kk++) {
            const int k = kk * 8;
            unsigned af[2][4];
            #pragma unroll
            for (int mi = 0; mi < 2; mi++) {
                int r = warp_m * 32 + mi * 16 + group;
                af[mi][0] = as_[r][k + tig];     af[mi][1] = as_[r + 8][k + tig];
                af[mi][2] = as_[r][k + tig + 4]; af[mi][3] = as_[r + 8][k + tig + 4];
            }
            unsigned bf[6][2];
            #pragma unroll
            for (int ni = 0; ni < 6; ni++) {
                int c = warp_n * 48 + ni * 8 + group;
                bf[ni][0] = bs_[k + tig][c];
                bf[ni][1] = bs_[k + tig + 4][c];
            }
            #pragma unroll
            for (int mi = 0; mi < 2; mi++)
                #pragma unroll
                for (int ni = 0; ni < 6; ni++)
                    mma8(acc[mi][ni], af[mi][0], af[mi][1], af[mi][2], af[mi][3],
                         bf[ni][0], bf[ni][1]);
        }
        __syncthreads();
    }

    #pragma unroll
    for (int mi = 0; mi < 2; mi++) {
        int r = row0 + warp_m * 32 + mi * 16 + group;
        #pragma unroll
        for (int ni = 0; ni < 6; ni++) {
            int col = warp_n * 48 + ni * 8 + 2 * tig;
            int p = col >> 6, c = col & 63;
            const float* bias = (p == 0) ? bq : (p == 1) ? bk : bv;
            float* outp      = (p == 0) ? g_q : (p == 1) ? g_k : g_v;
            float b0 = bias[c], b1 = bias[c + 1];
            *(float2*)&outp[(size_t)r * HH + c] =
                make_float2(acc[mi][ni][0] + b0, acc[mi][ni][1] + b1);
            *(float2*)&outp[(size_t)(r + 8) * HH + c] =
                make_float2(acc[mi][ni][2] + b0, acc[mi][ni][3] + b1);
        }
    }
}

// ---------------------------------------------------------------------------
// Kernel 2: scores -> unnormalized probs. Tile 128(j) x 128(i), K=64, tf32 MMA.
// 8 warps: 2(j) x 4(i), warp tile 64x32. Dynamic smem 69.6 KB.
// Writes exp(raw*0.125) (masked -> 0). No max subtraction: scores are bounded.
// ---------------------------------------------------------------------------
#define SC_SMEM (2 * 128 * 68 * 4)
__global__ __launch_bounds__(256) void scores_kernel()
{
    const int ti = blockIdx.x, tj = blockIdx.y, b = blockIdx.z;
    if (ti < tj) return;

    extern __shared__ unsigned dynsm[];
    unsigned (*qs_)[68] = (unsigned(*)[68])dynsm;                // [j][h], pad 4
    unsigned (*ks_)[68] = (unsigned(*)[68])(dynsm + 128 * 68);   // [i][h], pad 4

    const int tid = threadIdx.x;
    const int wid = tid >> 5, lane = tid & 31;
    const int group = lane >> 2, tig = lane & 3;
    const int warpj = wid >> 2;         // 0..1
    const int warpi = wid & 3;          // 0..3
    const int j0 = tj * 128, i0 = ti * 128;

    const float* qp = g_q + ((size_t)b * NN + j0) * HH;
    const float* kp = g_k + ((size_t)b * NN + i0) * HH;
    #pragma unroll
    for (int e = 0; e < 8; e++) {
        int id = tid + e * 256;                    // 2048 float4s (128 x 16)
        int r = id >> 4, c4 = id & 15;
        float4 q4 = *(const float4*)&qp[(size_t)r * HH + c4 * 4];
        float4 k4 = *(const float4*)&kp[(size_t)r * HH + c4 * 4];
        qs_[r][c4*4+0]=f2tf(q4.x); qs_[r][c4*4+1]=f2tf(q4.y);
        qs_[r][c4*4+2]=f2tf(q4.z); qs_[r][c4*4+3]=f2tf(q4.w);
        ks_[r][c4*4+0]=f2tf(k4.x); ks_[r][c4*4+1]=f2tf(k4.y);
        ks_[r][c4*4+2]=f2tf(k4.z); ks_[r][c4*4+3]=f2tf(k4.w);
    }
    __syncthreads();

    float acc[4][4][4] = {};
    #pragma unroll
    for (int kk = 0; kk < 8; kk++) {
        const int k = kk * 8;
        unsigned af[4][4];
        #pragma unroll
        for (int mi = 0; mi < 4; mi++) {
            int r = warpj * 64 + mi * 16 + group;
            af[mi][0] = qs_[r][k + tig];     af[mi][1] = qs_[r + 8][k + tig];
            af[mi][2] = qs_[r][k + tig + 4]; af[mi][3] = qs_[r + 8][k + tig + 4];
        }
        unsigned bf[4][2];
        #pragma unroll
        for (int ni = 0; ni < 4; ni++) {
            int c = warpi * 32 + ni * 8 + group;
            bf[ni][0] = ks_[c][k + tig];
            bf[ni][1] = ks_[c][k + tig + 4];
        }
        #pragma unroll
        for (int mi = 0; mi < 4; mi++)
            #pragma unroll
            for (int ni = 0; ni < 4; ni++)
                mma8(acc[mi][ni], af[mi][0], af[mi][1], af[mi][2], af[mi][3],
                     bf[ni][0], bf[ni][1]);
    }

    float* Sp = g_S + (size_t)b * NN * NN;
    #pragma unroll
    for (int mi = 0; mi < 4; mi++) {
        #pragma unroll
        for (int ni = 0; ni < 4; ni++) {
            int jA = j0 + warpj * 64 + mi * 16 + group;
            int iA = i0 + warpi * 32 + ni * 8 + 2 * tig;
            float v00 = acc[mi][ni][0], v01 = acc[mi][ni][1];
            float v10 = acc[mi][ni][2], v11 = acc[mi][ni][3];
            float e00 = (iA     < jA     || v00 == 0.0f) ? 0.0f : __expf(v00 * 0.125f);
            float e01 = (iA + 1 < jA     || v01 == 0.0f) ? 0.0f : __expf(v01 * 0.125f);
            float e10 = (iA     < jA + 8 || v10 == 0.0f) ? 0.0f : __expf(v10 * 0.125f);
            float e11 = (iA + 1 < jA + 8 || v11 == 0.0f) ? 0.0f : __expf(v11 * 0.125f);
            *(float2*)&Sp[(size_t)jA * NN + iA]       = make_float2(e00, e01);
            *(float2*)&Sp[(size_t)(jA + 8) * NN + iA] = make_float2(e10, e11);
        }
    }
}

// ---------------------------------------------------------------------------
// Kernel 3: row sums of unnormalized probs -> g_rZ = 1/Z. One warp per row.
// Entries below the diagonal are 0.0 in g_S, so summing extra is harmless.
// ---------------------------------------------------------------------------
__global__ __launch_bounds__(256) void sum_kernel()
{
    const int row = blockIdx.x * 8 + (threadIdx.x >> 5);
    const int lane = threadIdx.x & 31;
    const int b = row / NN, j = row % NN;
    const float* Sp = g_S + ((size_t)b * NN + j) * NN;

    float Z = 0.0f;
    for (int i = (j & ~31) + lane; i < NN; i += 32) Z += Sp[i];
    #pragma unroll
    for (int off = 16; off > 0; off >>= 1) Z += __shfl_xor_sync(0xffffffffu, Z, off);
    if (lane == 0) g_rZ[row] = (Z > 0.0f) ? 1.0f / Z : 0.0f;
}

// ---------------------------------------------------------------------------
// Kernel 4: out[b,i,h] = sum_j P[j,i] * (rZ[j]*v[j,h]), tf32 MMA.
// Tile 128(i) x 64(h), K-stage 64(j). 8 warps: 4(m) x 2(n), warp tile 32x32.
// rZ folded into V smem load. Split-K 4. Dynamic smem 53.2 KB.
// ---------------------------------------------------------------------------
#define PV_SMEM ((64 * 136 + 64 * 72) * 4)
__global__ __launch_bounds__(256) void pv_kernel()
{
    const int IT    = blockIdx.x;            // 0..15
    const int split = blockIdx.y;            // 0..3
    const int b     = blockIdx.z;
    const int n_jt  = 2 * IT + 2;
    const int chunk = (n_jt + SPLITS - 1) / SPLITS;
    const int jt0   = split * chunk;
    const int jt1   = min(n_jt, jt0 + chunk);

    extern __shared__ unsigned dynsm[];
    unsigned (*ps_)[136] = (unsigned(*)[136])dynsm;              // [j][i], B-style pad 8
    unsigned (*vs_)[72]  = (unsigned(*)[72])(dynsm + 64 * 136);  // [j][h], B-style pad 8

    const int tid = threadIdx.x;
    const int wid = tid >> 5, lane = tid & 31;
    const int group = lane >> 2, tig = lane & 3;
    const int warp_m = wid >> 1;        // 0..3  (32 i each)
    const int warp_n = wid & 1;         // 0..1  (32 h each)
    const int i0 = IT * 128;
    const float* Sp = g_S + (size_t)b * NN * NN;

    float acc[2][4][4] = {};

    for (int jt = jt0; jt < jt1; jt++) {
        const int j0 = jt * 64;
        #pragma unroll
        for (int e = 0; e < 8; e++) {
            int id = tid + e * 256;              // 2048 float4s (64j x 32 i-f4)
            int r = id >> 5, c4 = id & 31;
            float4 v = *(const float4*)&Sp[(size_t)(j0 + r) * NN + i0 + c4 * 4];
            ps_[r][c4*4+0] = f2tf(v.x); ps_[r][c4*4+1] = f2tf(v.y);
            ps_[r][c4*4+2] = f2tf(v.z); ps_[r][c4*4+3] = f2tf(v.w);
        }
        #pragma unroll
        for (int e = 0; e < 4; e++) {
            int id = tid + e * 256;              // 1024 float4s (64j x 16 h-f4)
            int r = id >> 4, c4 = id & 15;
            float rz = g_rZ[b * NN + j0 + r];
            float4 v = *(const float4*)&g_v[((size_t)b * NN + j0 + r) * HH + c4 * 4];
            vs_[r][c4*4+0] = f2tf(v.x * rz); vs_[r][c4*4+1] = f2tf(v.y * rz);
            vs_[r][c4*4+2] = f2tf(v.z * rz); vs_[r][c4*4+3] = f2tf(v.w * rz);
        }
        __syncthreads();

        #pragma unroll
        for (int kk = 0; kk < 8; kk++) {
            const int k = kk * 8;
            unsigned af[2][4];
            #pragma unroll
            for (int mi = 0; mi < 2; mi++) {
                int iL = warp_m * 32 + mi * 16 + group;
                af[mi][0] = ps_[k + tig][iL];     af[mi][1] = ps_[k + tig][iL + 8];
                af[mi][2] = ps_[k + tig + 4][iL]; af[mi][3] = ps_[k + tig + 4][iL + 8];
            }
            unsigned bf[4][2];
            #pragma unroll
            for (int ni = 0; ni < 4; ni++) {
                int h = warp_n * 32 + ni * 8 + group;
                bf[ni][0] = vs_[k + tig][h];
                bf[ni][1] = vs_[k + tig + 4][h];
            }
            #pragma unroll
            for (int mi = 0; mi < 2; mi++)
                #pragma unroll
                for (int ni = 0; ni < 4; ni++)
                    mma8(acc[mi][ni], af[mi][0], af[mi][1], af[mi][2], af[mi][3],
                         bf[ni][0], bf[ni][1]);
        }
        __syncthreads();
    }

    float* P = g_part[split];
    #pragma unroll
    for (int mi = 0; mi < 2; mi++) {
        #pragma unroll
        for (int ni = 0; ni < 4; ni++) {
            int iA = i0 + warp_m * 32 + mi * 16 + group;
            int h  = warp_n * 32 + ni * 8 + 2 * tig;
            *(float2*)&P[((size_t)b * NN + iA) * HH + h] =
                make_float2(acc[mi][ni][0], acc[mi][ni][1]);
            *(float2*)&P[((size_t)b * NN + iA + 8) * HH + h] =
                make_float2(acc[mi][ni][2], acc[mi][ni][3]);
        }
    }
}

// ---------------------------------------------------------------------------
// Kernel 5: reduce split-K partials
// ---------------------------------------------------------------------------
__global__ __launch_bounds__(256) void reduce_kernel(float* __restrict__ out)
{
    size_t idx = (size_t)blockIdx.x * 256 + threadIdx.x;
    float s = 0.0f;
    #pragma unroll
    for (int p = 0; p < SPLITS; p++) s += g_part[p][idx];
    out[idx] = s;
}

// ---------------------------------------------------------------------------
extern "C" void kernel_launch(void* const* d_in, const int* in_sizes, int n_in,
                              void* d_out, int out_size)
{
    const float* x  = (const float*)d_in[0];
    const float* Wq = (const float*)d_in[1];
    const float* bq = (const float*)d_in[2];
    const float* Wk = (const float*)d_in[3];
    const float* bk = (const float*)d_in[4];
    const float* Wv = (const float*)d_in[5];
    const float* bv = (const float*)d_in[6];
    float* out = (float*)d_out;

    // One-time opt-in for >48KB dynamic smem (first call only, outside capture).
    static bool attrs_set = false;
    if (!attrs_set) {
        cudaFuncSetAttribute(scores_kernel, cudaFuncAttributeMaxDynamicSharedMemorySize, SC_SMEM);
        cudaFuncSetAttribute(pv_kernel,     cudaFuncAttributeMaxDynamicSharedMemorySize, PV_SMEM);
        attrs_set = true;
    }

    qkv_kernel<<<dim3(M_TOT / 64), 256>>>(x, Wq, bq, Wk, bk, Wv, bv);
    scores_kernel<<<dim3(NN / 128, NN / 128, BB), 256, SC_SMEM>>>();
    sum_kernel<<<M_TOT / 8, 256>>>();
    pv_kernel<<<dim3(NN / 128, SPLITS, BB), 256, PV_SMEM>>>();
    reduce_kernel<<<(M_TOT * HH) / 256, 256>>>(out);
}

// round 7
// speedup vs baseline: 3.3230x; 1.0496x over previous
#include <cuda_runtime.h>
#include <math.h>

#define BB 4
#define NN 2048
#define DD 1024
#define HH 64
#define M_TOT (BB*NN)
#define SPLITS 4

static __device__ float g_q[M_TOT*HH];
static __device__ float g_k[M_TOT*HH];
static __device__ float g_v[M_TOT*HH];
static __device__ float g_Zp[M_TOT*4];             // partial row sums (4 i-splits)
static __device__ float g_rZ[M_TOT];               // 1/rowsum
static __device__ float g_part[SPLITS][M_TOT*HH];  // split-K partials for PV

// ---------------------------------------------------------------------------
// TF32 helpers
// ---------------------------------------------------------------------------
__device__ __forceinline__ unsigned f2tf(float f) {
    unsigned u; asm("cvt.rna.tf32.f32 %0, %1;" : "=r"(u) : "f"(f)); return u;
}
__device__ __forceinline__ void mma8(float c[4],
                                     unsigned a0, unsigned a1, unsigned a2, unsigned a3,
                                     unsigned b0, unsigned b1) {
    asm volatile(
        "mma.sync.aligned.m16n8k8.row.col.f32.tf32.tf32.f32 "
        "{%0,%1,%2,%3}, {%4,%5,%6,%7}, {%8,%9}, {%0,%1,%2,%3};"
        : "+f"(c[0]), "+f"(c[1]), "+f"(c[2]), "+f"(c[3])
        : "r"(a0), "r"(a1), "r"(a2), "r"(a3), "r"(b0), "r"(b1));
}

// ---------------------------------------------------------------------------
// Kernel 1: fused QKV projection, tf32 MMA (unchanged from R6).
// ---------------------------------------------------------------------------
__global__ __launch_bounds__(256) void qkv_kernel(
    const float* __restrict__ x,
    const float* __restrict__ Wq, const float* __restrict__ bq,
    const float* __restrict__ Wk, const float* __restrict__ bk,
    const float* __restrict__ Wv, const float* __restrict__ bv)
{
    __shared__ unsigned as_[64][36];
    __shared__ unsigned bs_[32][200];

    const int tid = threadIdx.x;
    const int wid = tid >> 5, lane = tid & 31;
    const int group = lane >> 2, tig = lane & 3;
    const int warp_m = wid >> 2;
    const int warp_n = wid & 3;
    const int row0 = blockIdx.x * 64;

    float acc[2][6][4] = {};

    for (int kt = 0; kt < DD; kt += 32) {
        #pragma unroll
        for (int e = 0; e < 2; e++) {
            int id = tid + e * 256;
            int r = id >> 3, c4 = id & 7;
            float4 v = *(const float4*)&x[(size_t)(row0 + r) * DD + kt + c4 * 4];
            as_[r][c4*4+0] = f2tf(v.x); as_[r][c4*4+1] = f2tf(v.y);
            as_[r][c4*4+2] = f2tf(v.z); as_[r][c4*4+3] = f2tf(v.w);
        }
        #pragma unroll
        for (int p = 0; p < 3; p++) {
            const float* W = (p == 0) ? Wq : (p == 1) ? Wk : Wv;
            #pragma unroll
            for (int e = 0; e < 2; e++) {
                int id = tid + e * 256;
                int r = id >> 4, c4 = id & 15;
                float4 v = *(const float4*)&W[(size_t)(kt + r) * HH + c4 * 4];
                bs_[r][p*64 + c4*4+0] = f2tf(v.x); bs_[r][p*64 + c4*4+1] = f2tf(v.y);
                bs_[r][p*64 + c4*4+2] = f2tf(v.z); bs_[r][p*64 + c4*4+3] = f2tf(v.w);
            }
        }
        __syncthreads();

        #pragma unroll
        for (int kk = 0; kk < 4; kk++) {
            const int k = kk * 8;
            unsigned af[2][4];
            #pragma unroll
            for (int mi = 0; mi < 2; mi++) {
                int r = warp_m * 32 + mi * 16 + group;
                af[mi][0] = as_[r][k + tig];     af[mi][1] = as_[r + 8][k + tig];
                af[mi][2] = as_[r][k + tig + 4]; af[mi][3] = as_[r + 8][k + tig + 4];
            }
            unsigned bf[6][2];
            #pragma unroll
            for (int ni = 0; ni < 6; ni++) {
                int c = warp_n * 48 + ni * 8 + group;
                bf[ni][0] = bs_[k + tig][c];
                bf[ni][1] = bs_[k + tig + 4][c];
            }
            #pragma unroll
            for (int mi = 0; mi < 2; mi++)
                #pragma unroll
                for (int ni = 0; ni < 6; ni++)
                    mma8(acc[mi][ni], af[mi][0], af[mi][1], af[mi][2], af[mi][3],
                         bf[ni][0], bf[ni][1]);
        }
        __syncthreads();
    }

    #pragma unroll
    for (int mi = 0; mi < 2; mi++) {
        int r = row0 + warp_m * 32 + mi * 16 + group;
        #pragma unroll
        for (int ni = 0; ni < 6; ni++) {
            int col = warp_n * 48 + ni * 8 + 2 * tig;
            int p = col >> 6, c = col & 63;
            const float* bias = (p == 0) ? bq : (p == 1) ? bk : bv;
            float* outp      = (p == 0) ? g_q : (p == 1) ? g_k : g_v;
            float b0 = bias[c], b1 = bias[c + 1];
            *(float2*)&outp[(size_t)r * HH + c] =
                make_float2(acc[mi][ni][0] + b0, acc[mi][ni][1] + b1);
            *(float2*)&outp[(size_t)(r + 8) * HH + c] =
                make_float2(acc[mi][ni][2] + b0, acc[mi][ni][3] + b1);
        }
    }
}

// ---------------------------------------------------------------------------
// Kernel 2: zsum. Per j-tile (128), recompute score tiles over i >= j,
// exp, accumulate row sums in registers -> partial Z per i-split. No S store.
// grid (tj=16, isplit=4, b=4), 8 warps = 2(j) x 4(i).
// ---------------------------------------------------------------------------
#define ZS_SMEM ((2 * 128 * 68 + 4 * 128) * 4)
__global__ __launch_bounds__(256) void zsum_kernel()
{
    const int tj = blockIdx.x, isplit = blockIdx.y, b = blockIdx.z;

    extern __shared__ unsigned dynsm[];
    unsigned (*qs_)[68] = (unsigned(*)[68])dynsm;              // [j][h], pad 4
    unsigned (*ks_)[68] = (unsigned(*)[68])(dynsm + 128 * 68); // [i][h], pad 4
    float* zsh = (float*)(dynsm + 2 * 128 * 68);               // [4 warpi][128 j]

    const int tid = threadIdx.x;
    const int wid = tid >> 5, lane = tid & 31;
    const int group = lane >> 2, tig = lane & 3;
    const int warpj = wid >> 2;         // 0..1 (64 j each)
    const int warpi = wid & 3;          // 0..3 (32 i each)
    const int j0 = tj * 128;

    const float* qp = g_q + ((size_t)b * NN + j0) * HH;
    #pragma unroll
    for (int e = 0; e < 8; e++) {
        int id = tid + e * 256;                    // 2048 float4s
        int r = id >> 4, c4 = id & 15;
        float4 q4 = *(const float4*)&qp[(size_t)r * HH + c4 * 4];
        qs_[r][c4*4+0]=f2tf(q4.x); qs_[r][c4*4+1]=f2tf(q4.y);
        qs_[r][c4*4+2]=f2tf(q4.z); qs_[r][c4*4+3]=f2tf(q4.w);
    }

    const int count = 16 - tj;
    const int chunk = (count + 3) >> 2;
    const int it0 = tj + isplit * chunk;
    const int it1 = min(16, it0 + chunk);

    float zacc[4][2] = {};

    for (int it = it0; it < it1; it++) {
        __syncthreads();       // protect ks_ (prior iter reads / qs_ stores on first iter)
        const float* kp = g_k + ((size_t)b * NN + it * 128) * HH;
        #pragma unroll
        for (int e = 0; e < 8; e++) {
            int id = tid + e * 256;
            int r = id >> 4, c4 = id & 15;
            float4 k4 = *(const float4*)&kp[(size_t)r * HH + c4 * 4];
            ks_[r][c4*4+0]=f2tf(k4.x); ks_[r][c4*4+1]=f2tf(k4.y);
            ks_[r][c4*4+2]=f2tf(k4.z); ks_[r][c4*4+3]=f2tf(k4.w);
        }
        __syncthreads();

        float acc[4][4][4] = {};
        #pragma unroll
        for (int kk = 0; kk < 8; kk++) {
            const int k = kk * 8;
            unsigned af[4][4];
            #pragma unroll
            for (int mi = 0; mi < 4; mi++) {
                int r = warpj * 64 + mi * 16 + group;
                af[mi][0] = qs_[r][k + tig];     af[mi][1] = qs_[r + 8][k + tig];
                af[mi][2] = qs_[r][k + tig + 4]; af[mi][3] = qs_[r + 8][k + tig + 4];
            }
            unsigned bf[4][2];
            #pragma unroll
            for (int ni = 0; ni < 4; ni++) {
                int c = warpi * 32 + ni * 8 + group;
                bf[ni][0] = ks_[c][k + tig];
                bf[ni][1] = ks_[c][k + tig + 4];
            }
            #pragma unroll
            for (int mi = 0; mi < 4; mi++)
                #pragma unroll
                for (int ni = 0; ni < 4; ni++)
                    mma8(acc[mi][ni], af[mi][0], af[mi][1], af[mi][2], af[mi][3],
                         bf[ni][0], bf[ni][1]);
        }

        const int i0 = it * 128;
        #pragma unroll
        for (int mi = 0; mi < 4; mi++) {
            #pragma unroll
            for (int ni = 0; ni < 4; ni++) {
                int jA = j0 + warpj * 64 + mi * 16 + group;
                int iA = i0 + warpi * 32 + ni * 8 + 2 * tig;
                float v00 = acc[mi][ni][0], v01 = acc[mi][ni][1];
                float v10 = acc[mi][ni][2], v11 = acc[mi][ni][3];
                float e00 = (iA     < jA     || v00 == 0.0f) ? 0.0f : __expf(v00 * 0.125f);
                float e01 = (iA + 1 < jA     || v01 == 0.0f) ? 0.0f : __expf(v01 * 0.125f);
                float e10 = (iA     < jA + 8 || v10 == 0.0f) ? 0.0f : __expf(v10 * 0.125f);
                float e11 = (iA + 1 < jA + 8 || v11 == 0.0f) ? 0.0f : __expf(v11 * 0.125f);
                zacc[mi][0] += e00 + e01;
                zacc[mi][1] += e10 + e11;
            }
        }
    }

    // reduce over tig (quad) -> warp partial per row
    #pragma unroll
    for (int mi = 0; mi < 4; mi++) {
        float s0 = zacc[mi][0], s1 = zacc[mi][1];
        s0 += __shfl_xor_sync(0xffffffffu, s0, 1);
        s0 += __shfl_xor_sync(0xffffffffu, s0, 2);
        s1 += __shfl_xor_sync(0xffffffffu, s1, 1);
        s1 += __shfl_xor_sync(0xffffffffu, s1, 2);
        zacc[mi][0] = s0; zacc[mi][1] = s1;
    }
    __syncthreads();
    if (tig == 0) {
        #pragma unroll
        for (int mi = 0; mi < 4; mi++) {
            int jl = warpj * 64 + mi * 16 + group;
            zsh[warpi * 128 + jl]     = zacc[mi][0];
            zsh[warpi * 128 + jl + 8] = zacc[mi][1];
        }
    }
    __syncthreads();
    if (tid < 128) {
        float z = zsh[tid] + zsh[128 + tid] + zsh[256 + tid] + zsh[384 + tid];
        g_Zp[(((size_t)b * NN) + j0 + tid) * 4 + isplit] = z;
    }
}

// ---------------------------------------------------------------------------
// Kernel 3: combine partial Z -> g_rZ = 1/Z
// ---------------------------------------------------------------------------
__global__ __launch_bounds__(256) void zcombine_kernel()
{
    int row = blockIdx.x * 256 + threadIdx.x;
    float z = g_Zp[row*4+0] + g_Zp[row*4+1] + g_Zp[row*4+2] + g_Zp[row*4+3];
    g_rZ[row] = (z > 0.0f) ? 1.0f / z : 0.0f;
}

// ---------------------------------------------------------------------------
// Kernel 4: fused PV. Per (i-tile 128, split, b): K i-tile resident; per
// j-tile 64: MMA1 recomputes scores (64j x 128i), exp -> tf32 P in smem,
// MMA2 accumulates P^T x (V*rZ) into out[128i x 64h]. No S gmem traffic.
// MMA1 warps: 2(j) x 4(i). MMA2 warps: 4(i) x 2(h). Split-K 4.
// ---------------------------------------------------------------------------
#define PV_SMEM ((128*68 + 64*68 + 64*72 + 64*136) * 4)
__global__ __launch_bounds__(256) void pv_kernel()
{
    const int IT    = blockIdx.x;            // 0..15
    const int split = blockIdx.y;            // 0..3
    const int b     = blockIdx.z;
    const int n_jt  = 2 * IT + 2;
    const int chunk = (n_jt + SPLITS - 1) / SPLITS;
    const int jt0   = split * chunk;
    const int jt1   = min(n_jt, jt0 + chunk);

    extern __shared__ unsigned dynsm[];
    unsigned (*ks_)[68]  = (unsigned(*)[68])dynsm;                          // [i][h]
    unsigned (*qs_)[68]  = (unsigned(*)[68])(dynsm + 128*68);               // [j][h]
    unsigned (*vs_)[72]  = (unsigned(*)[72])(dynsm + 128*68 + 64*68);       // [j][h]
    unsigned (*ps_)[136] = (unsigned(*)[136])(dynsm + 128*68 + 64*68 + 64*72); // [j][i]

    const int tid = threadIdx.x;
    const int wid = tid >> 5, lane = tid & 31;
    const int group = lane >> 2, tig = lane & 3;
    // MMA1 mapping
    const int warpj = wid >> 2;         // 0..1 (32 j each)
    const int warpi = wid & 3;          // 0..3 (32 i each)
    // MMA2 mapping
    const int warp_m = wid >> 1;        // 0..3 (32 i each)
    const int warp_n = wid & 1;         // 0..1 (32 h each)
    const int i0 = IT * 128;

    // K i-tile resident for the whole block
    const float* kp = g_k + ((size_t)b * NN + i0) * HH;
    #pragma unroll
    for (int e = 0; e < 8; e++) {
        int id = tid + e * 256;                    // 2048 float4s
        int r = id >> 4, c4 = id & 15;
        float4 k4 = *(const float4*)&kp[(size_t)r * HH + c4 * 4];
        ks_[r][c4*4+0]=f2tf(k4.x); ks_[r][c4*4+1]=f2tf(k4.y);
        ks_[r][c4*4+2]=f2tf(k4.z); ks_[r][c4*4+3]=f2tf(k4.w);
    }

    float acc[2][4][4] = {};

    for (int jt = jt0; jt < jt1; jt++) {
        const int j0 = jt * 64;
        __syncthreads();   // protect qs/vs/ps from prior stage reads (and ks stores, iter 0)
        const float* qp = g_q + ((size_t)b * NN + j0) * HH;
        #pragma unroll
        for (int e = 0; e < 4; e++) {
            int id = tid + e * 256;                // 1024 float4s (64j x 16 h-f4)
            int r = id >> 4, c4 = id & 15;
            float4 q4 = *(const float4*)&qp[(size_t)r * HH + c4 * 4];
            qs_[r][c4*4+0]=f2tf(q4.x); qs_[r][c4*4+1]=f2tf(q4.y);
            qs_[r][c4*4+2]=f2tf(q4.z); qs_[r][c4*4+3]=f2tf(q4.w);
        }
        #pragma unroll
        for (int e = 0; e < 4; e++) {
            int id = tid + e * 256;
            int r = id >> 4, c4 = id & 15;
            float rz = g_rZ[b * NN + j0 + r];
            float4 v = *(const float4*)&g_v[((size_t)b * NN + j0 + r) * HH + c4 * 4];
            vs_[r][c4*4+0] = f2tf(v.x * rz); vs_[r][c4*4+1] = f2tf(v.y * rz);
            vs_[r][c4*4+2] = f2tf(v.z * rz); vs_[r][c4*4+3] = f2tf(v.w * rz);
        }
        __syncthreads();

        // ---- MMA1: scores s[64j x 128i] over k=64h ----
        float acc1[2][4][4] = {};
        #pragma unroll
        for (int kk = 0; kk < 8; kk++) {
            const int k = kk * 8;
            unsigned af[2][4];
            #pragma unroll
            for (int mi = 0; mi < 2; mi++) {
                int r = warpj * 32 + mi * 16 + group;
                af[mi][0] = qs_[r][k + tig];     af[mi][1] = qs_[r + 8][k + tig];
                af[mi][2] = qs_[r][k + tig + 4]; af[mi][3] = qs_[r + 8][k + tig + 4];
            }
            unsigned bf[4][2];
            #pragma unroll
            for (int ni = 0; ni < 4; ni++) {
                int c = warpi * 32 + ni * 8 + group;
                bf[ni][0] = ks_[c][k + tig];
                bf[ni][1] = ks_[c][k + tig + 4];
            }
            #pragma unroll
            for (int mi = 0; mi < 2; mi++)
                #pragma unroll
                for (int ni = 0; ni < 4; ni++)
                    mma8(acc1[mi][ni], af[mi][0], af[mi][1], af[mi][2], af[mi][3],
                         bf[ni][0], bf[ni][1]);
        }

        // ---- exp + mask -> P tile (tf32) in smem ----
        #pragma unroll
        for (int mi = 0; mi < 2; mi++) {
            #pragma unroll
            for (int ni = 0; ni < 4; ni++) {
                int jl = warpj * 32 + mi * 16 + group;
                int il = warpi * 32 + ni * 8 + 2 * tig;
                int jA = j0 + jl, iA = i0 + il;
                float v00 = acc1[mi][ni][0], v01 = acc1[mi][ni][1];
                float v10 = acc1[mi][ni][2], v11 = acc1[mi][ni][3];
                float e00 = (iA     < jA     || v00 == 0.0f) ? 0.0f : __expf(v00 * 0.125f);
                float e01 = (iA + 1 < jA     || v01 == 0.0f) ? 0.0f : __expf(v01 * 0.125f);
                float e10 = (iA     < jA + 8 || v10 == 0.0f) ? 0.0f : __expf(v10 * 0.125f);
                float e11 = (iA + 1 < jA + 8 || v11 == 0.0f) ? 0.0f : __expf(v11 * 0.125f);
                uint2 lo = make_uint2(f2tf(e00), f2tf(e01));
                uint2 hi = make_uint2(f2tf(e10), f2tf(e11));
                *(uint2*)&ps_[jl][il]     = lo;
                *(uint2*)&ps_[jl + 8][il] = hi;
            }
        }
        __syncthreads();

        // ---- MMA2: out[128i x 64h] += P^T x (V*rZ), k=64j ----
        #pragma unroll
        for (int kk = 0; kk < 8; kk++) {
            const int k = kk * 8;
            unsigned af[2][4];
            #pragma unroll
            for (int mi = 0; mi < 2; mi++) {
                int iL = warp_m * 32 + mi * 16 + group;
                af[mi][0] = ps_[k + tig][iL];     af[mi][1] = ps_[k + tig][iL + 8];
                af[mi][2] = ps_[k + tig + 4][iL]; af[mi][3] = ps_[k + tig + 4][iL + 8];
            }
            unsigned bf[4][2];
            #pragma unroll
            for (int ni = 0; ni < 4; ni++) {
                int h = warp_n * 32 + ni * 8 + group;
                bf[ni][0] = vs_[k + tig][h];
                bf[ni][1] = vs_[k + tig + 4][h];
            }
            #pragma unroll
            for (int mi = 0; mi < 2; mi++)
                #pragma unroll
                for (int ni = 0; ni < 4; ni++)
                    mma8(acc[mi][ni], af[mi][0], af[mi][1], af[mi][2], af[mi][3],
                         bf[ni][0], bf[ni][1]);
        }
    }

    float* P = g_part[split];
    #pragma unroll
    for (int mi = 0; mi < 2; mi++) {
        #pragma unroll
        for (int ni = 0; ni < 4; ni++) {
            int iA = i0 + warp_m * 32 + mi * 16 + group;
            int h  = warp_n * 32 + ni * 8 + 2 * tig;
            *(float2*)&P[((size_t)b * NN + iA) * HH + h] =
                make_float2(acc[mi][ni][0], acc[mi][ni][1]);
            *(float2*)&P[((size_t)b * NN + iA + 8) * HH + h] =
                make_float2(acc[mi][ni][2], acc[mi][ni][3]);
        }
    }
}

// ---------------------------------------------------------------------------
// Kernel 5: reduce split-K partials
// ---------------------------------------------------------------------------
__global__ __launch_bounds__(256) void reduce_kernel(float* __restrict__ out)
{
    size_t idx = (size_t)blockIdx.x * 256 + threadIdx.x;
    float s = 0.0f;
    #pragma unroll
    for (int p = 0; p < SPLITS; p++) s += g_part[p][idx];
    out[idx] = s;
}

// ---------------------------------------------------------------------------
extern "C" void kernel_launch(void* const* d_in, const int* in_sizes, int n_in,
                              void* d_out, int out_size)
{
    const float* x  = (const float*)d_in[0];
    const float* Wq = (const float*)d_in[1];
    const float* bq = (const float*)d_in[2];
    const float* Wk = (const float*)d_in[3];
    const float* bk = (const float*)d_in[4];
    const float* Wv = (const float*)d_in[5];
    const float* bv = (const float*)d_in[6];
    float* out = (float*)d_out;

    static bool attrs_set = false;
    if (!attrs_set) {
        cudaFuncSetAttribute(zsum_kernel, cudaFuncAttributeMaxDynamicSharedMemorySize, ZS_SMEM);
        cudaFuncSetAttribute(pv_kernel,   cudaFuncAttributeMaxDynamicSharedMemorySize, PV_SMEM);
        attrs_set = true;
    }

    qkv_kernel<<<dim3(M_TOT / 64), 256>>>(x, Wq, bq, Wk, bk, Wv, bv);
    zsum_kernel<<<dim3(NN / 128, 4, BB), 256, ZS_SMEM>>>();
    zcombine_kernel<<<M_TOT / 256, 256>>>();
    pv_kernel<<<dim3(NN / 128, SPLITS, BB), 256, PV_SMEM>>>();
    reduce_kernel<<<(M_TOT * HH) / 256, 256>>>(out);
}

// round 9
// speedup vs baseline: 3.5998x; 1.0833x over previous
#include <cuda_runtime.h>
#include <math.h>

#define BB 4
#define NN 2048
#define DD 1024
#define HH 64
#define M_TOT (BB*NN)
#define SPLITS 8

static __device__ float g_q[M_TOT*HH];
static __device__ float g_k[M_TOT*HH];
static __device__ float g_v[M_TOT*HH];
static __device__ float g_Zp[M_TOT*4];             // partial row sums (4 i-splits)
static __device__ float g_rZ[M_TOT];               // 1/rowsum
static __device__ float g_part[SPLITS][M_TOT*HH];  // split-K partials for PV

// ---------------------------------------------------------------------------
// TF32 helpers
// ---------------------------------------------------------------------------
__device__ __forceinline__ unsigned f2tf(float f) {
    unsigned u; asm("cvt.rna.tf32.f32 %0, %1;" : "=r"(u) : "f"(f)); return u;
}
__device__ __forceinline__ void mma8(float c[4],
                                     unsigned a0, unsigned a1, unsigned a2, unsigned a3,
                                     unsigned b0, unsigned b1) {
    asm volatile(
        "mma.sync.aligned.m16n8k8.row.col.f32.tf32.tf32.f32 "
        "{%0,%1,%2,%3}, {%4,%5,%6,%7}, {%8,%9}, {%0,%1,%2,%3};"
        : "+f"(c[0]), "+f"(c[1]), "+f"(c[2]), "+f"(c[3])
        : "r"(a0), "r"(a1), "r"(a2), "r"(a3), "r"(b0), "r"(b1));
}

// ---------------------------------------------------------------------------
// Kernel 1: fused QKV projection, tf32 MMA (unchanged).
// ---------------------------------------------------------------------------
__global__ __launch_bounds__(256) void qkv_kernel(
    const float* __restrict__ x,
    const float* __restrict__ Wq, const float* __restrict__ bq,
    const float* __restrict__ Wk, const float* __restrict__ bk,
    const float* __restrict__ Wv, const float* __restrict__ bv)
{
    __shared__ unsigned as_[64][36];
    __shared__ unsigned bs_[32][200];

    const int tid = threadIdx.x;
    const int wid = tid >> 5, lane = tid & 31;
    const int group = lane >> 2, tig = lane & 3;
    const int warp_m = wid >> 2;
    const int warp_n = wid & 3;
    const int row0 = blockIdx.x * 64;

    float acc[2][6][4] = {};

    for (int kt = 0; kt < DD; kt += 32) {
        #pragma unroll
        for (int e = 0; e < 2; e++) {
            int id = tid + e * 256;
            int r = id >> 3, c4 = id & 7;
            float4 v = *(const float4*)&x[(size_t)(row0 + r) * DD + kt + c4 * 4];
            as_[r][c4*4+0] = f2tf(v.x); as_[r][c4*4+1] = f2tf(v.y);
            as_[r][c4*4+2] = f2tf(v.z); as_[r][c4*4+3] = f2tf(v.w);
        }
        #pragma unroll
        for (int p = 0; p < 3; p++) {
            const float* W = (p == 0) ? Wq : (p == 1) ? Wk : Wv;
            #pragma unroll
            for (int e = 0; e < 2; e++) {
                int id = tid + e * 256;
                int r = id >> 4, c4 = id & 15;
                float4 v = *(const float4*)&W[(size_t)(kt + r) * HH + c4 * 4];
                bs_[r][p*64 + c4*4+0] = f2tf(v.x); bs_[r][p*64 + c4*4+1] = f2tf(v.y);
                bs_[r][p*64 + c4*4+2] = f2tf(v.z); bs_[r][p*64 + c4*4+3] = f2tf(v.w);
            }
        }
        __syncthreads();

        #pragma unroll
        for (int kk = 0; kk < 4; kk++) {
            const int k = kk * 8;
            unsigned af[2][4];
            #pragma unroll
            for (int mi = 0; mi < 2; mi++) {
                int r = warp_m * 32 + mi * 16 + group;
                af[mi][0] = as_[r][k + tig];     af[mi][1] = as_[r + 8][k + tig];
                af[mi][2] = as_[r][k + tig + 4]; af[mi][3] = as_[r + 8][k + tig + 4];
            }
            unsigned bf[6][2];
            #pragma unroll
            for (int ni = 0; ni < 6; ni++) {
                int c = warp_n * 48 + ni * 8 + group;
                bf[ni][0] = bs_[k + tig][c];
                bf[ni][1] = bs_[k + tig + 4][c];
            }
            #pragma unroll
            for (int mi = 0; mi < 2; mi++)
                #pragma unroll
                for (int ni = 0; ni < 6; ni++)
                    mma8(acc[mi][ni], af[mi][0], af[mi][1], af[mi][2], af[mi][3],
                         bf[ni][0], bf[ni][1]);
        }
        __syncthreads();
    }

    #pragma unroll
    for (int mi = 0; mi < 2; mi++) {
        int r = row0 + warp_m * 32 + mi * 16 + group;
        #pragma unroll
        for (int ni = 0; ni < 6; ni++) {
            int col = warp_n * 48 + ni * 8 + 2 * tig;
            int p = col >> 6, c = col & 63;
            const float* bias = (p == 0) ? bq : (p == 1) ? bk : bv;
            float* outp      = (p == 0) ? g_q : (p == 1) ? g_k : g_v;
            float b0 = bias[c], b1 = bias[c + 1];
            *(float2*)&outp[(size_t)r * HH + c] =
                make_float2(acc[mi][ni][0] + b0, acc[mi][ni][1] + b1);
            *(float2*)&outp[(size_t)(r + 8) * HH + c] =
                make_float2(acc[mi][ni][2] + b0, acc[mi][ni][3] + b1);
        }
    }
}

// ---------------------------------------------------------------------------
// Kernel 2: zsum (unchanged). Recompute score tiles, exp, row sums.
// ---------------------------------------------------------------------------
#define ZS_SMEM ((2 * 128 * 68 + 4 * 128) * 4)
__global__ __launch_bounds__(256) void zsum_kernel()
{
    const int tj = blockIdx.x, isplit = blockIdx.y, b = blockIdx.z;

    extern __shared__ unsigned dynsm[];
    unsigned (*qs_)[68] = (unsigned(*)[68])dynsm;
    unsigned (*ks_)[68] = (unsigned(*)[68])(dynsm + 128 * 68);
    float* zsh = (float*)(dynsm + 2 * 128 * 68);

    const int tid = threadIdx.x;
    const int wid = tid >> 5, lane = tid & 31;
    const int group = lane >> 2, tig = lane & 3;
    const int warpj = wid >> 2;
    const int warpi = wid & 3;
    const int j0 = tj * 128;

    const float* qp = g_q + ((size_t)b * NN + j0) * HH;
    #pragma unroll
    for (int e = 0; e < 8; e++) {
        int id = tid + e * 256;
        int r = id >> 4, c4 = id & 15;
        float4 q4 = *(const float4*)&qp[(size_t)r * HH + c4 * 4];
        qs_[r][c4*4+0]=f2tf(q4.x); qs_[r][c4*4+1]=f2tf(q4.y);
        qs_[r][c4*4+2]=f2tf(q4.z); qs_[r][c4*4+3]=f2tf(q4.w);
    }

    const int count = 16 - tj;
    const int chunk = (count + 3) >> 2;
    const int it0 = tj + isplit * chunk;
    const int it1 = min(16, it0 + chunk);

    float zacc[4][2] = {};

    for (int it = it0; it < it1; it++) {
        __syncthreads();
        const float* kp = g_k + ((size_t)b * NN + it * 128) * HH;
        #pragma unroll
        for (int e = 0; e < 8; e++) {
            int id = tid + e * 256;
            int r = id >> 4, c4 = id & 15;
            float4 k4 = *(const float4*)&kp[(size_t)r * HH + c4 * 4];
            ks_[r][c4*4+0]=f2tf(k4.x); ks_[r][c4*4+1]=f2tf(k4.y);
            ks_[r][c4*4+2]=f2tf(k4.z); ks_[r][c4*4+3]=f2tf(k4.w);
        }
        __syncthreads();

        float acc[4][4][4] = {};
        #pragma unroll
        for (int kk = 0; kk < 8; kk++) {
            const int k = kk * 8;
            unsigned af[4][4];
            #pragma unroll
            for (int mi = 0; mi < 4; mi++) {
                int r = warpj * 64 + mi * 16 + group;
                af[mi][0] = qs_[r][k + tig];     af[mi][1] = qs_[r + 8][k + tig];
                af[mi][2] = qs_[r][k + tig + 4]; af[mi][3] = qs_[r + 8][k + tig + 4];
            }
            unsigned bf[4][2];
            #pragma unroll
            for (int ni = 0; ni < 4; ni++) {
                int c = warpi * 32 + ni * 8 + group;
                bf[ni][0] = ks_[c][k + tig];
                bf[ni][1] = ks_[c][k + tig + 4];
            }
            #pragma unroll
            for (int mi = 0; mi < 4; mi++)
                #pragma unroll
                for (int ni = 0; ni < 4; ni++)
                    mma8(acc[mi][ni], af[mi][0], af[mi][1], af[mi][2], af[mi][3],
                         bf[ni][0], bf[ni][1]);
        }

        const int i0 = it * 128;
        #pragma unroll
        for (int mi = 0; mi < 4; mi++) {
            #pragma unroll
            for (int ni = 0; ni < 4; ni++) {
                int jA = j0 + warpj * 64 + mi * 16 + group;
                int iA = i0 + warpi * 32 + ni * 8 + 2 * tig;
                float v00 = acc[mi][ni][0], v01 = acc[mi][ni][1];
                float v10 = acc[mi][ni][2], v11 = acc[mi][ni][3];
                float e00 = (iA     < jA     || v00 == 0.0f) ? 0.0f : __expf(v00 * 0.125f);
                float e01 = (iA + 1 < jA     || v01 == 0.0f) ? 0.0f : __expf(v01 * 0.125f);
                float e10 = (iA     < jA + 8 || v10 == 0.0f) ? 0.0f : __expf(v10 * 0.125f);
                float e11 = (iA + 1 < jA + 8 || v11 == 0.0f) ? 0.0f : __expf(v11 * 0.125f);
                zacc[mi][0] += e00 + e01;
                zacc[mi][1] += e10 + e11;
            }
        }
    }

    #pragma unroll
    for (int mi = 0; mi < 4; mi++) {
        float s0 = zacc[mi][0], s1 = zacc[mi][1];
        s0 += __shfl_xor_sync(0xffffffffu, s0, 1);
        s0 += __shfl_xor_sync(0xffffffffu, s0, 2);
        s1 += __shfl_xor_sync(0xffffffffu, s1, 1);
        s1 += __shfl_xor_sync(0xffffffffu, s1, 2);
        zacc[mi][0] = s0; zacc[mi][1] = s1;
    }
    __syncthreads();
    if (tig == 0) {
        #pragma unroll
        for (int mi = 0; mi < 4; mi++) {
            int jl = warpj * 64 + mi * 16 + group;
            zsh[warpi * 128 + jl]     = zacc[mi][0];
            zsh[warpi * 128 + jl + 8] = zacc[mi][1];
        }
    }
    __syncthreads();
    if (tid < 128) {
        float z = zsh[tid] + zsh[128 + tid] + zsh[256 + tid] + zsh[384 + tid];
        g_Zp[(((size_t)b * NN) + j0 + tid) * 4 + isplit] = z;
    }
}

// ---------------------------------------------------------------------------
// Kernel 3: combine partial Z -> g_rZ = 1/Z
// ---------------------------------------------------------------------------
__global__ __launch_bounds__(256) void zcombine_kernel()
{
    int row = blockIdx.x * 256 + threadIdx.x;
    float z = g_Zp[row*4+0] + g_Zp[row*4+1] + g_Zp[row*4+2] + g_Zp[row*4+3];
    g_rZ[row] = (z > 0.0f) ? 1.0f / z : 0.0f;
}

// ---------------------------------------------------------------------------
// Kernel 4: fused PV, 512 threads / 16 warps for latency hiding.
// Per (i-tile 128, split, b): K resident; per j-tile 64:
//   MMA1 (warps 4j x 4i): scores 64j x 128i -> exp -> tf32 P in smem
//   MMA2 (warps 4i x 4h): out[128i x 64h] += P^T x (V*rZ)
// Split-K 8.
// ---------------------------------------------------------------------------
#define PV_SMEM ((128*68 + 64*68 + 64*72 + 64*136) * 4)
__global__ __launch_bounds__(512) void pv_kernel()
{
    const int IT    = blockIdx.x;            // 0..15
    const int split = blockIdx.y;            // 0..7
    const int b     = blockIdx.z;
    const int n_jt  = 2 * IT + 2;
    const int chunk = (n_jt + SPLITS - 1) / SPLITS;
    const int jt0   = split * chunk;
    const int jt1   = min(n_jt, jt0 + chunk);

    extern __shared__ unsigned dynsm[];
    unsigned (*ks_)[68]  = (unsigned(*)[68])dynsm;                              // [i][h]
    unsigned (*qs_)[68]  = (unsigned(*)[68])(dynsm + 128*68);                   // [j][h]
    unsigned (*vs_)[72]  = (unsigned(*)[72])(dynsm + 128*68 + 64*68);           // [j][h]
    unsigned (*ps_)[136] = (unsigned(*)[136])(dynsm + 128*68 + 64*68 + 64*72);  // [j][i]

    const int tid = threadIdx.x;
    const int wid = tid >> 5, lane = tid & 31;
    const int group = lane >> 2, tig = lane & 3;
    // MMA1: 4(j) x 4(i); warp tile 16j x 32i
    const int warpj = wid >> 2;         // 0..3
    const int warpi = wid & 3;          // 0..3
    // MMA2: 4(i) x 4(h); warp tile 32i x 16h
    const int warp_m = wid >> 2;        // 0..3
    const int warp_n = wid & 3;         // 0..3
    const int i0 = IT * 128;

    // K i-tile resident for the whole block
    const float* kp = g_k + ((size_t)b * NN + i0) * HH;
    #pragma unroll
    for (int e = 0; e < 4; e++) {
        int id = tid + e * 512;                    // 2048 float4s
        int r = id >> 4, c4 = id & 15;
        float4 k4 = *(const float4*)&kp[(size_t)r * HH + c4 * 4];
        ks_[r][c4*4+0]=f2tf(k4.x); ks_[r][c4*4+1]=f2tf(k4.y);
        ks_[r][c4*4+2]=f2tf(k4.z); ks_[r][c4*4+3]=f2tf(k4.w);
    }

    float acc[2][2][4] = {};

    for (int jt = jt0; jt < jt1; jt++) {
        const int j0 = jt * 64;
        __syncthreads();   // protect qs/vs/ps from prior-iter reads (and ks_ stores, iter 0)
        const float* qp = g_q + ((size_t)b * NN + j0) * HH;
        #pragma unroll
        for (int e = 0; e < 2; e++) {
            int id = tid + e * 512;                // 1024 float4s (64j x 16 h-f4)
            int r = id >> 4, c4 = id & 15;
            float4 q4 = *(const float4*)&qp[(size_t)r * HH + c4 * 4];
            qs_[r][c4*4+0]=f2tf(q4.x); qs_[r][c4*4+1]=f2tf(q4.y);
            qs_[r][c4*4+2]=f2tf(q4.z); qs_[r][c4*4+3]=f2tf(q4.w);
        }
        #pragma unroll
        for (int e = 0; e < 2; e++) {
            int id = tid + e * 512;
            int r = id >> 4, c4 = id & 15;
            float rz = g_rZ[b * NN + j0 + r];
            float4 v = *(const float4*)&g_v[((size_t)b * NN + j0 + r) * HH + c4 * 4];
            vs_[r][c4*4+0] = f2tf(v.x * rz); vs_[r][c4*4+1] = f2tf(v.y * rz);
            vs_[r][c4*4+2] = f2tf(v.z * rz); vs_[r][c4*4+3] = f2tf(v.w * rz);
        }
        __syncthreads();

        // ---- MMA1: scores s[64j x 128i] over k=64h; warp tile 16j x 32i ----
        float acc1[4][4] = {};
        #pragma unroll
        for (int kk = 0; kk < 8; kk++) {
            const int k = kk * 8;
            unsigned af[4];
            {
                int r = warpj * 16 + group;
                af[0] = qs_[r][k + tig];     af[1] = qs_[r + 8][k + tig];
                af[2] = qs_[r][k + tig + 4]; af[3] = qs_[r + 8][k + tig + 4];
            }
            unsigned bf[4][2];
            #pragma unroll
            for (int ni = 0; ni < 4; ni++) {
                int c = warpi * 32 + ni * 8 + group;
                bf[ni][0] = ks_[c][k + tig];
                bf[ni][1] = ks_[c][k + tig + 4];
            }
            #pragma unroll
            for (int ni = 0; ni < 4; ni++)
                mma8(acc1[ni], af[0], af[1], af[2], af[3], bf[ni][0], bf[ni][1]);
        }

        // ---- exp + mask -> P tile (tf32) in smem ----
        #pragma unroll
        for (int ni = 0; ni < 4; ni++) {
            int jl = warpj * 16 + group;
            int il = warpi * 32 + ni * 8 + 2 * tig;
            int jA = j0 + jl, iA = i0 + il;
            float v00 = acc1[ni][0], v01 = acc1[ni][1];
            float v10 = acc1[ni][2], v11 = acc1[ni][3];
            float e00 = (iA     < jA     || v00 == 0.0f) ? 0.0f : __expf(v00 * 0.125f);
            float e01 = (iA + 1 < jA     || v01 == 0.0f) ? 0.0f : __expf(v01 * 0.125f);
            float e10 = (iA     < jA + 8 || v10 == 0.0f) ? 0.0f : __expf(v10 * 0.125f);
            float e11 = (iA + 1 < jA + 8 || v11 == 0.0f) ? 0.0f : __expf(v11 * 0.125f);
            *(uint2*)&ps_[jl][il]     = make_uint2(f2tf(e00), f2tf(e01));
            *(uint2*)&ps_[jl + 8][il] = make_uint2(f2tf(e10), f2tf(e11));
        }
        __syncthreads();

        // ---- MMA2: out[128i x 64h] += P^T x (V*rZ), k=64j; warp tile 32i x 16h ----
        #pragma unroll
        for (int kk = 0; kk < 8; kk++) {
            const int k = kk * 8;
            unsigned af[2][4];
            #pragma unroll
            for (int mi = 0; mi < 2; mi++) {
                int iL = warp_m * 32 + mi * 16 + group;
                af[mi][0] = ps_[k + tig][iL];     af[mi][1] = ps_[k + tig][iL + 8];
                af[mi][2] = ps_[k + tig + 4][iL]; af[mi][3] = ps_[k + tig + 4][iL + 8];
            }
            unsigned bf[2][2];
            #pragma unroll
            for (int ni = 0; ni < 2; ni++) {
                int h = warp_n * 16 + ni * 8 + group;
                bf[ni][0] = vs_[k + tig][h];
                bf[ni][1] = vs_[k + tig + 4][h];
            }
            #pragma unroll
            for (int mi = 0; mi < 2; mi++)
                #pragma unroll
                for (int ni = 0; ni < 2; ni++)
                    mma8(acc[mi][ni], af[mi][0], af[mi][1], af[mi][2], af[mi][3],
                         bf[ni][0], bf[ni][1]);
        }
    }

    float* P = g_part[split];
    #pragma unroll
    for (int mi = 0; mi < 2; mi++) {
        #pragma unroll
        for (int ni = 0; ni < 2; ni++) {
            int iA = i0 + warp_m * 32 + mi * 16 + group;
            int h  = warp_n * 16 + ni * 8 + 2 * tig;
            *(float2*)&P[((size_t)b * NN + iA) * HH + h] =
                make_float2(acc[mi][ni][0], acc[mi][ni][1]);
            *(float2*)&P[((size_t)b * NN + iA + 8) * HH + h] =
                make_float2(acc[mi][ni][2], acc[mi][ni][3]);
        }
    }
}

// ---------------------------------------------------------------------------
// Kernel 5: reduce split-K partials
// ---------------------------------------------------------------------------
__global__ __launch_bounds__(256) void reduce_kernel(float* __restrict__ out)
{
    size_t idx = (size_t)blockIdx.x * 256 + threadIdx.x;
    float s = 0.0f;
    #pragma unroll
    for (int p = 0; p < SPLITS; p++) s += g_part[p][idx];
    out[idx] = s;
}

// ---------------------------------------------------------------------------
extern "C" void kernel_launch(void* const* d_in, const int* in_sizes, int n_in,
                              void* d_out, int out_size)
{
    const float* x  = (const float*)d_in[0];
    const float* Wq = (const float*)d_in[1];
    const float* bq = (const float*)d_in[2];
    const float* Wk = (const float*)d_in[3];
    const float* bk = (const float*)d_in[4];
    const float* Wv = (const float*)d_in[5];
    const float* bv = (const float*)d_in[6];
    float* out = (float*)d_out;

    static bool attrs_set = false;
    if (!attrs_set) {
        cudaFuncSetAttribute(zsum_kernel, cudaFuncAttributeMaxDynamicSharedMemorySize, ZS_SMEM);
        cudaFuncSetAttribute(pv_kernel,   cudaFuncAttributeMaxDynamicSharedMemorySize, PV_SMEM);
        attrs_set = true;
    }

    qkv_kernel<<<dim3(M_TOT / 64), 256>>>(x, Wq, bq, Wk, bk, Wv, bv);
    zsum_kernel<<<dim3(NN / 128, 4, BB), 256, ZS_SMEM>>>();
    zcombine_kernel<<<M_TOT / 256, 256>>>();
    pv_kernel<<<dim3(NN / 128, SPLITS, BB), 512, PV_SMEM>>>();
    reduce_kernel<<<(M_TOT * HH) / 256, 256>>>(out);
}